// round 11
// baseline (speedup 1.0000x reference)
#include <cuda_runtime.h>

namespace {
constexpr int B = 2, H = 128, W = 256, MD = 34, LD = 32;
constexpr int NH = 4, SH = 64, K = 25, P = 7, R = 3;
constexpr int FF1 = 512, FF2 = 256;
constexpr int PP = P * P; // 49
constexpr long M_PIX = (long)B * H * W; // 65536

// ---------------- disco mma kernel config ----------------
constexpr int TW   = 32;
constexpr int PIX  = 8;
constexpr int NGRP = TW / PIX;
constexpr int TAD  = 256;           // 8 warps, 2 m16-tiles per warp
constexpr int XCOLS = TW + 2 * R;   // 38
constexpr int PR   = 8;             // padded stencil rows (row 7 = zeros)

constexpr int WEFFB_F = 8 * 7 * 32 * 2;      // 3584
constexpr int HW1B_F  = 4 * 4 * 8 * 32 * 2;  // 8192
constexpr int FW1B_F  = 64 * 5 * 32 * 2;     // 20480 (k padded 34->40)
constexpr int FW2B_F  = 16 * 32 * 4 * 32 * 2;// 131072
constexpr int FW3B_F  = 4 * 32 * 32 * 2;     // 8192

// disco smem (floats)
constexpr int OFF_SX   = 0;                          // 32*8*38 = 9728
constexpr int OFF_SXC  = OFF_SX + LD * PR * XCOLS;   // 1024
constexpr int OFF_SDB  = OFF_SXC + LD * TW;          // 64
constexpr int OFF_HB1  = OFF_SDB + SH;               // 128
constexpr int OFF_HW2  = OFF_HB1 + NH * 32;          // 128
constexpr int OFF_HB2  = OFF_HW2 + NH * 32;          // 4
constexpr int SMEM_D_F = OFF_HB2 + NH;               // 11076 fl = 44.3 KB

__device__ __forceinline__ float gelu_exact(float v) {
    return 0.5f * v * (1.0f + erff(v * 0.70710678118654752440f));
}

__device__ __forceinline__ float f2tf_f(float f) {
    unsigned u;
    asm("cvt.rna.tf32.f32 %0, %1;" : "=r"(u) : "f"(f));
    return __uint_as_float(u);
}

__device__ __forceinline__ void mma_tf32(float c[4], const float4& a, const float2& b) {
    const unsigned* A = reinterpret_cast<const unsigned*>(&a);
    const unsigned* Bv = reinterpret_cast<const unsigned*>(&b);
    asm volatile(
        "mma.sync.aligned.m16n8k8.row.col.f32.tf32.tf32.f32 "
        "{%0,%1,%2,%3},{%4,%5,%6,%7},{%8,%9},{%0,%1,%2,%3};\n"
        : "+f"(c[0]), "+f"(c[1]), "+f"(c[2]), "+f"(c[3])
        : "r"(A[0]), "r"(A[1]), "r"(A[2]), "r"(A[3]), "r"(Bv[0]), "r"(Bv[1]));
}
} // namespace

// device-global scratch (no runtime allocation)
// g_t1: stage-1 output in tiled A-frag layout:
//   float idx = ((rowtile*64 + kc*4 + ks)*32 + lane)*4 + rg
__device__ __align__(16) float g_t1[M_PIX * FF1];   // 128 MB
__device__ __align__(16) float g_weffB[H * WEFFB_F];
__device__ __align__(16) float g_hw1B[HW1B_F];
__device__ __align__(16) float g_fw1B[FW1B_F];
__device__ __align__(16) float g_fw2B[FW2B_F];
__device__ __align__(16) float g_fw3B[FW3B_F];

// =====================================================================
// prep: fold psi into disco_w per latitude (B-frag layout, rounded)
// =====================================================================
__global__ void prep_weffB(const float* __restrict__ dw,
                           const float* __restrict__ psi) {
    const int h = blockIdx.x;
    for (int e = threadIdx.x; e < WEFFB_F; e += blockDim.x) {
        int half = e & 1, t = e >> 1;
        int lane = t & 31; t >>= 5;
        int ks = t % 7, nt = t / 7;
        int g = lane >> 2, tg = lane & 3;
        int p = ks * 8 + tg + 4 * half;
        int s = nt * 8 + g;
        float acc = 0.f;
        if (p < PP) {
            #pragma unroll
            for (int k = 0; k < K; k++)
                acc += dw[s * K + k] * psi[(k * H + h) * PP + p];
        }
        g_weffB[h * WEFFB_F + e] = f2tf_f(acc);
    }
}

// =====================================================================
// prep: hw1 / fw1 / fw3 into B-frag layouts, rounded (merged kernel)
// =====================================================================
__global__ void prep_small(const float* __restrict__ hw1,
                           const float* __restrict__ fw1,
                           const float* __restrict__ fw3) {
    int e = blockIdx.x * blockDim.x + threadIdx.x;
    if (e < HW1B_F) {
        int half = e & 1, t = e >> 1;
        int lane = t & 31; t >>= 5;
        int ks = t & 7; t >>= 3;
        int nt = t & 3; int n = t >> 2;
        int g = lane >> 2, tg = lane & 3;
        int s = ks * 8 + tg + 4 * half;
        int o = nt * 8 + g;
        g_hw1B[e] = f2tf_f(hw1[(n * SH + s) * 32 + o]);
        return;
    }
    e -= HW1B_F;
    if (e < FW1B_F) {
        int half = e & 1, t = e >> 1;
        int lane = t & 31; t >>= 5;
        int ks = t % 5, nt = t / 5;
        int g = lane >> 2, tg = lane & 3;
        int k = ks * 8 + tg + 4 * half;
        int n = nt * 8 + g;
        g_fw1B[e] = (k < MD) ? f2tf_f(fw1[k * FF1 + n]) : 0.f;
        return;
    }
    e -= FW1B_F;
    if (e < FW3B_F) {
        int half = e & 1, t = e >> 1;
        int lane = t & 31; t >>= 5;
        int ks = t & 31, nt = t >> 5;
        int g = lane >> 2, tg = lane & 3;
        int k = ks * 8 + tg + 4 * half;
        int n = nt * 8 + g;
        g_fw3B[e] = f2tf_f(fw3[k * LD + n]);
    }
}

// =====================================================================
// prep: fw2 into per-chunk B-frag layout, rounded
// =====================================================================
__global__ void prep_fw2B(const float* __restrict__ fw2) {
    int e = blockIdx.x * blockDim.x + threadIdx.x;
    if (e >= FW2B_F) return;
    int kc = e >> 13, r = e & 8191;
    int half = r & 1; r >>= 1;
    int lane = r & 31; r >>= 5;
    int ks = r & 3; int nt = r >> 2;
    int g = lane >> 2, tg = lane & 3;
    int k = kc * 32 + ks * 8 + tg + 4 * half;
    int n = nt * 8 + g;
    g_fw2B[e] = f2tf_f(fw2[k * FF2 + n]);
}

// =====================================================================
// disco conv + head MLP + residual (tf32 mma)
// 8 warps x 2 m16-tiles; stencil padded to 8 rows (row 7 zero) so the
// a-operand build needs no predication.
// =====================================================================
__global__ __launch_bounds__(TAD, 2) void disco_head_mma(
    const float* __restrict__ x,   const float* __restrict__ db,
    const float* __restrict__ hb1, const float* __restrict__ hw2,
    const float* __restrict__ hb2, float* __restrict__ out)
{
    extern __shared__ float sm[];
    float* sx   = sm + OFF_SX;
    float* sxc  = sm + OFF_SXC;
    float* sdb  = sm + OFF_SDB;
    float* shb1 = sm + OFF_HB1;
    float* shw2 = sm + OFF_HW2;
    float* shb2 = sm + OFF_HB2;

    const int tid = threadIdx.x;
    const int lane = tid & 31, mt = tid >> 5;    // mt 0..7
    const int g  = lane >> 2, tg = lane & 3;
    const int w0 = blockIdx.x * TW;
    const int h  = blockIdx.y;
    const int b  = blockIdx.z;

    if (tid < SH) sdb[tid] = db[tid];
    if (tid < NH * 32) { shb1[tid] = hb1[tid]; shw2[tid] = hw2[tid]; }
    if (tid < NH) shb2[tid] = hb2[tid];

    // stencil tile: rounded into sx rows 0..6; row 7 zeroed; exact center
    // taps into sxc (residual)
    for (int i = tid; i < LD * P * XCOLS; i += TAD) {
        int ld = i & 31; int pos = i >> 5;
        int r = pos / XCOLS, c = pos % XCOLS;
        int lat = h + r - R; lat = lat < 0 ? 0 : (lat > H - 1 ? H - 1 : lat);
        int lon = (w0 + c - R + W) & (W - 1);
        float v = x[((b * H + lat) * W + lon) * MD + ld];
        sx[(ld * PR + r) * XCOLS + c] = f2tf_f(v);
        if (r == R && c >= R && c < R + TW) sxc[ld * TW + (c - R)] = v;
    }
    for (int i = tid; i < LD * XCOLS; i += TAD) {
        int ld = i & 31, c = i >> 5;
        sx[(ld * PR + 7) * XCOLS + c] = 0.f;
    }
    for (int i = tid; i < TW * 2; i += TAD) {
        int px = i >> 1, j = i & 1;
        int gi = ((b * H + h) * W + (w0 + px)) * MD + LD + j;
        out[gi] = x[gi];
    }
    __syncthreads();

    // warp mt owns tiles t0=2mt, t1=2mt+1 -> same head nh = mt>>1,
    // rows = lds ldA..ldA+3 where ldA = nh*8 + 4*(mt&1)
    const int nh  = mt >> 1;
    const int ldA = nh * 8 + 4 * (mt & 1);
    const int px  = g;
    const int base0 = (ldA + 0) * PR * XCOLS;
    const int base1 = (ldA + 1) * PR * XCOLS;
    const int base2 = (ldA + 2) * PR * XCOLS;
    const int base3 = (ldA + 3) * PR * XCOLS;

    int roff0[7], roff1[7];
    #pragma unroll
    for (int ks = 0; ks < 7; ks++) {
        int p0 = ks * 8 + tg, p1 = p0 + 4;
        roff0[ks] = (p0 / 7) * XCOLS + (p0 % 7);   // p>=49 lands in zero row 7
        roff1[ks] = (p1 / 7) * XCOLS + (p1 % 7);
    }

    const float2* swB2  = reinterpret_cast<const float2*>(g_weffB) + (long)h * (WEFFB_F / 2);
    const float2* hw1b2 = reinterpret_cast<const float2*>(g_hw1B);

    // shuffle sources for C-frag -> A-frag relayout
    const int src0 = (lane & ~3) | (tg >> 1);
    const int src1 = src0 + 2;
    const bool odd = (tg & 1);

    for (int grp = 0; grp < NGRP; grp++) {
        const int cbase = grp * PIX + px;
        const int cb0 = base0 + cbase, cb1 = base1 + cbase;
        const int cb2 = base2 + cbase, cb3 = base3 + cbase;

        // phase 1: d = taps @ weff  (two m16 tiles, N=64, K=56)
        float c1[2][8][4] = {};
        #pragma unroll
        for (int ks = 0; ks < 7; ks++) {
            float4 a0, a1;
            a0.x = sx[cb0 + roff0[ks]];
            a0.y = sx[cb1 + roff0[ks]];
            a0.z = sx[cb0 + roff1[ks]];
            a0.w = sx[cb1 + roff1[ks]];
            a1.x = sx[cb2 + roff0[ks]];
            a1.y = sx[cb3 + roff0[ks]];
            a1.z = sx[cb2 + roff1[ks]];
            a1.w = sx[cb3 + roff1[ks]];
            #pragma unroll
            for (int nt = 0; nt < 8; nt++) {
                float2 bb = __ldg(&swB2[(nt * 7 + ks) * 32 + lane]);
                mma_tf32(c1[0][nt], a0, bb);
                mma_tf32(c1[1][nt], a1, bb);
            }
        }

        // phase 2 fused: per k8-block, bias+round, shuffle C->A frag (both
        // tiles), then each hw1 fragment load feeds 2 MMAs.
        float c2[2][4][4] = {};
        #pragma unroll
        for (int ks = 0; ks < 8; ks++) {
            const int scol = ks * 8 + 2 * tg;
            const float b0 = sdb[scol], b1 = sdb[scol + 1];
            float4 af[2];
            #pragma unroll
            for (int t = 0; t < 2; t++) {
                const float y0 = f2tf_f(c1[t][ks][0] + b0);
                const float y1 = f2tf_f(c1[t][ks][1] + b1);
                const float y2 = f2tf_f(c1[t][ks][2] + b0);
                const float y3 = f2tf_f(c1[t][ks][3] + b1);
                const float u0 = __shfl_sync(0xffffffffu, y0, src0);
                const float u1 = __shfl_sync(0xffffffffu, y1, src0);
                const float u2 = __shfl_sync(0xffffffffu, y2, src0);
                const float u3 = __shfl_sync(0xffffffffu, y3, src0);
                const float v0 = __shfl_sync(0xffffffffu, y0, src1);
                const float v1 = __shfl_sync(0xffffffffu, y1, src1);
                const float v2 = __shfl_sync(0xffffffffu, y2, src1);
                const float v3 = __shfl_sync(0xffffffffu, y3, src1);
                af[t].x = odd ? u1 : u0;
                af[t].y = odd ? u3 : u2;
                af[t].z = odd ? v1 : v0;
                af[t].w = odd ? v3 : v2;
            }
            #pragma unroll
            for (int nt2 = 0; nt2 < 4; nt2++) {
                float2 bb = __ldg(&hw1b2[((nh * 4 + nt2) * 8 + ks) * 32 + lane]);
                mma_tf32(c2[0][nt2], af[0], bb);
                mma_tf32(c2[1][nt2], af[1], bb);
            }
        }

        // epilogue 2: gelu + hw2 dot + lane reduce + residual (fp32 path)
        #pragma unroll
        for (int t = 0; t < 2; t++) {
            float part0 = 0.f, part1 = 0.f;
            #pragma unroll
            for (int nt2 = 0; nt2 < 4; nt2++) {
                const int o0 = nt2 * 8 + 2 * tg, o1 = o0 + 1;
                const float w0v = shw2[nh * 32 + o0], w1v = shw2[nh * 32 + o1];
                const float bb0 = shb1[nh * 32 + o0], bb1 = shb1[nh * 32 + o1];
                part0 += gelu_exact(c2[t][nt2][0] + bb0) * w0v
                       + gelu_exact(c2[t][nt2][1] + bb1) * w1v;
                part1 += gelu_exact(c2[t][nt2][2] + bb0) * w0v
                       + gelu_exact(c2[t][nt2][3] + bb1) * w1v;
            }
            part0 += __shfl_xor_sync(0xffffffffu, part0, 1);
            part0 += __shfl_xor_sync(0xffffffffu, part0, 2);
            part1 += __shfl_xor_sync(0xffffffffu, part1, 1);
            part1 += __shfl_xor_sync(0xffffffffu, part1, 2);
            if (tg == 0) {
                const int ld0 = ldA + 2 * t, ld1 = ld0 + 1;
                const int pxg = grp * PIX + px;
                const float v0 = part0 + shb2[nh] + sxc[ld0 * TW + pxg];
                const float v1 = part1 + shb2[nh] + sxc[ld1 * TW + pxg];
                const long o = ((long)(b * H + h) * W + w0 + pxg) * MD;
                out[o + ld0] = v0;
                out[o + ld1] = v1;
            }
        }
    }
}

// =====================================================================
// FFN stage 1: g_t1(frag) = gelu(out[:,:34] @ fw1 + fb1)
// =====================================================================
namespace {
constexpr int S1_AF = 4 * 5 * 32 * 4;   // 2560
constexpr int S1_BF = 32 * 5 * 32 * 2;  // 10240
}
__global__ __launch_bounds__(512) void ffn_s1(
    const float* __restrict__ xin, const float* __restrict__ fb1)
{
    extern __shared__ float sm[];
    float* sA = sm;
    float* sB = sm + S1_AF;
    const int tid = threadIdx.x, lane = tid & 31, w = tid >> 5;
    const int mw = w >> 2, nw = w & 3;
    const long r0 = (long)blockIdx.x * 64;
    const int  n0 = blockIdx.y * 256;

    {
        const int r = tid >> 3, rr7 = r & 7, rhi = (r >> 3) & 1, mt = r >> 4;
        const int kb = (tid & 7) * 5;
        #pragma unroll
        for (int j = 0; j < 5; j++) {
            const int k = kb + j;
            const float v = (k < MD) ? f2tf_f(xin[(r0 + r) * MD + k]) : 0.f;
            sA[((mt * 5 + (k >> 3)) * 32 + rr7 * 4 + (k & 3)) * 4
               + rhi + (((k >> 2) & 1) << 1)] = v;
        }
    }
    {
        const float4* src = reinterpret_cast<const float4*>(g_fw1B + blockIdx.y * S1_BF);
        float4* dst = reinterpret_cast<float4*>(sB);
        #pragma unroll
        for (int i = 0; i < 5; i++) dst[tid + i * 512] = src[tid + i * 512];
    }
    __syncthreads();

    float c[8][4] = {};
    #pragma unroll
    for (int ks = 0; ks < 5; ks++) {
        float4 a = reinterpret_cast<const float4*>(sA)[(mw * 5 + ks) * 32 + lane];
        #pragma unroll
        for (int ni = 0; ni < 8; ni++) {
            float2 bb = reinterpret_cast<const float2*>(sB)[((nw * 8 + ni) * 5 + ks) * 32 + lane];
            mma_tf32(c[ni], a, bb);
        }
    }

    const int g = lane >> 2, tg = lane & 3;
    const long rt = blockIdx.x * 4 + mw;
    float2* t1v2 = reinterpret_cast<float2*>(g_t1);
    #pragma unroll
    for (int ni = 0; ni < 8; ni++) {
        const int n = n0 + (nw * 8 + ni) * 8 + 2 * tg;
        const int kc = n >> 5, ks2 = (n >> 3) & 3;
        const int kk0 = n & 7, kk1 = kk0 + 1;
        const long base = (rt * 64 + kc * 4 + ks2) * 32;
        const int rgA = ((kk0 >> 2) & 1) << 1;
        const long i0 = (base + g * 4 + (kk0 & 3)) * 4 + rgA;
        const long i1 = (base + g * 4 + (kk1 & 3)) * 4 + rgA;
        const float b0 = fb1[n], b1 = fb1[n + 1];
        t1v2[i0 >> 1] = make_float2(f2tf_f(gelu_exact(c[ni][0] + b0)),
                                    f2tf_f(gelu_exact(c[ni][2] + b0)));
        t1v2[i1 >> 1] = make_float2(f2tf_f(gelu_exact(c[ni][1] + b1)),
                                    f2tf_f(gelu_exact(c[ni][3] + b1)));
    }
}

// =====================================================================
// FFN stages 2+3 fused. Smem reworked to 96 KB -> 2 CTAs/SM:
// mainloop double-buffers in [0, 20480); afterwards sT2 overlays [0,16384)
// and fw3 frags are staged late into [16384, 24576).
// =====================================================================
namespace {
constexpr int S2_AF  = 4 * 4 * 32 * 4;     // 2048
constexpr int S2_BF  = 32 * 4 * 32 * 2;    // 8192
constexpr int S2_BUF = S2_AF + S2_BF;      // 10240
constexpr int ST2_F  = 4 * 32 * 32 * 4;    // 16384
constexpr int SF3_F  = 4 * 32 * 32 * 2;    // 8192
constexpr int S23_F  = ST2_F + SF3_F;      // 24576 floats = 96 KB
}
__global__ __launch_bounds__(512, 2) void ffn_s2s3(
    const float* __restrict__ fb2, const float* __restrict__ fb3,
    float* __restrict__ out)
{
    extern __shared__ float sm[];
    const int tid = threadIdx.x, lane = tid & 31, w = tid >> 5;
    const int mw = w >> 2, nw = w & 3;
    const long r0 = (long)blockIdx.x * 64;
    const long rt0 = (long)blockIdx.x * 4;

    float c[8][4] = {};
    const float4* t1v4 = reinterpret_cast<const float4*>(g_t1);
    const float4* fw2v4 = reinterpret_cast<const float4*>(g_fw2B);

    for (int kc = 0; kc < 16; kc++) {
        float* sA = sm + (kc & 1) * S2_BUF;
        float* sB = sA + S2_AF;
        reinterpret_cast<float4*>(sA)[tid] =
            t1v4[(rt0 + (tid >> 7)) * 2048 + kc * 128 + (tid & 127)];
        {
            float4* dst = reinterpret_cast<float4*>(sB);
            #pragma unroll
            for (int i = 0; i < 4; i++)
                dst[tid + i * 512] = fw2v4[kc * 2048 + tid + i * 512];
        }
        __syncthreads();
        #pragma unroll
        for (int ks = 0; ks < 4; ks++) {
            float4 a = reinterpret_cast<const float4*>(sA)[(mw * 4 + ks) * 32 + lane];
            #pragma unroll
            for (int ni = 0; ni < 8; ni++) {
                float2 bb = reinterpret_cast<const float2*>(sB)[((nw * 8 + ni) * 4 + ks) * 32 + lane];
                mma_tf32(c[ni], a, bb);
            }
        }
        __syncthreads();
    }

    // sT2 overlays the dead buffers; fw3 frags staged late behind it
    float* sT2 = sm;
    float* sf3 = sm + ST2_F;
    {
        const float4* src = reinterpret_cast<const float4*>(g_fw3B);
        float4* dst = reinterpret_cast<float4*>(sf3);
        #pragma unroll
        for (int i = 0; i < 4; i++) dst[tid + i * 512] = src[tid + i * 512];
    }
    float2* sT2v2 = reinterpret_cast<float2*>(sT2);
    const int g = lane >> 2, tg = lane & 3;
    #pragma unroll
    for (int ni = 0; ni < 8; ni++) {
        const int nt = nw * 8 + ni;
        const int n2 = nt * 8 + 2 * tg;
        const int kk0 = n2 & 7, kk1 = kk0 + 1;
        const int base = (mw * 32 + nt) * 32;
        const int rgA = ((kk0 >> 2) & 1) << 1;
        const int i0 = (base + g * 4 + (kk0 & 3)) * 4 + rgA;
        const int i1 = (base + g * 4 + (kk1 & 3)) * 4 + rgA;
        const float b0 = fb2[n2], b1 = fb2[n2 + 1];
        sT2v2[i0 >> 1] = make_float2(f2tf_f(gelu_exact(c[ni][0] + b0)),
                                     f2tf_f(gelu_exact(c[ni][2] + b0)));
        sT2v2[i1 >> 1] = make_float2(f2tf_f(gelu_exact(c[ni][1] + b1)),
                                     f2tf_f(gelu_exact(c[ni][3] + b1)));
    }
    __syncthreads();

    float c3[4] = {};
    #pragma unroll
    for (int ks = 0; ks < 32; ks++) {
        float4 a = reinterpret_cast<const float4*>(sT2)[(mw * 32 + ks) * 32 + lane];
        float2 bb = reinterpret_cast<const float2*>(sf3)[(nw * 32 + ks) * 32 + lane];
        mma_tf32(c3, a, bb);
    }

    const int col = nw * 8 + 2 * tg;
    const long rlo = r0 + mw * 16 + g, rhi = rlo + 8;
    const float b0 = fb3[col], b1 = fb3[col + 1];
    out[rlo * MD + col]     += c3[0] + b0;
    out[rlo * MD + col + 1] += c3[1] + b1;
    out[rhi * MD + col]     += c3[2] + b0;
    out[rhi * MD + col + 1] += c3[3] + b1;
}

extern "C" void kernel_launch(void* const* d_in, const int* in_sizes, int n_in,
                              void* d_out, int out_size) {
    const float* x   = (const float*)d_in[0];
    const float* psi = (const float*)d_in[1];
    const float* dw  = (const float*)d_in[2];
    const float* db  = (const float*)d_in[3];
    const float* hw1 = (const float*)d_in[4];
    const float* hb1 = (const float*)d_in[5];
    const float* hw2 = (const float*)d_in[6];
    const float* hb2 = (const float*)d_in[7];
    const float* fw1 = (const float*)d_in[8];
    const float* fb1 = (const float*)d_in[9];
    const float* fw2 = (const float*)d_in[10];
    const float* fb2 = (const float*)d_in[11];
    const float* fw3 = (const float*)d_in[12];
    const float* fb3 = (const float*)d_in[13];
    float* out = (float*)d_out;

    const size_t smD  = SMEM_D_F * sizeof(float);
    const size_t sm1  = (S1_AF + S1_BF) * sizeof(float);
    const size_t sm23 = S23_F * sizeof(float);
    cudaFuncSetAttribute(disco_head_mma, cudaFuncAttributeMaxDynamicSharedMemorySize, (int)smD);
    cudaFuncSetAttribute(ffn_s1, cudaFuncAttributeMaxDynamicSharedMemorySize, (int)sm1);
    cudaFuncSetAttribute(ffn_s2s3, cudaFuncAttributeMaxDynamicSharedMemorySize, (int)sm23);

    prep_weffB<<<H, 256>>>(dw, psi);
    prep_small<<<(HW1B_F + FW1B_F + FW3B_F + 255) / 256, 256>>>(hw1, fw1, fw3);
    prep_fw2B<<<FW2B_F / 256, 256>>>(fw2);
    disco_head_mma<<<dim3(W / TW, H, B), TAD, smD>>>(x, db, hb1, hw2, hb2, out);
    ffn_s1<<<dim3((unsigned)(M_PIX / 64), 2), 512, sm1>>>(out, fb1);
    ffn_s2s3<<<(unsigned)(M_PIX / 64), 512, sm23>>>(fb2, fb3, out);
}

// round 12
// speedup vs baseline: 1.2306x; 1.2306x over previous
#include <cuda_runtime.h>

namespace {
constexpr int B = 2, H = 128, W = 256, MD = 34, LD = 32;
constexpr int NH = 4, SH = 64, K = 25, P = 7, R = 3;
constexpr int FF1 = 512, FF2 = 256;
constexpr int PP = P * P; // 49
constexpr long M_PIX = (long)B * H * W; // 65536

// ---------------- disco mma kernel config (R10 configuration) ----------------
constexpr int TW   = 32;
constexpr int PIX  = 8;
constexpr int NGRP = TW / PIX;
constexpr int TAD  = 256;           // 8 warps, 2 m16-tiles per warp
constexpr int XCOLS = TW + 2 * R;   // 38

constexpr int WEFFB_F = 8 * 7 * 32 * 2;      // 3584
constexpr int HW1B_F  = 4 * 4 * 8 * 32 * 2;  // 8192
constexpr int FW1B_F  = 64 * 5 * 32 * 2;     // 20480 (k padded 34->40)
constexpr int FW2B_F  = 16 * 32 * 4 * 32 * 2;// 131072
constexpr int FW3B_F  = 4 * 32 * 32 * 2;     // 8192

// disco smem (floats): sx(rounded, 7 rows) + sxc(exact center) + small
constexpr int OFF_SX   = 0;                         // 8512
constexpr int OFF_SXC  = OFF_SX + LD * P * XCOLS;   // 1024
constexpr int OFF_SDB  = OFF_SXC + LD * TW;         // 64
constexpr int OFF_HB1  = OFF_SDB + SH;              // 128
constexpr int OFF_HW2  = OFF_HB1 + NH * 32;         // 128
constexpr int OFF_HB2  = OFF_HW2 + NH * 32;         // 4
constexpr int SMEM_D_F = OFF_HB2 + NH;              // 9860 fl = 39.4 KB

__device__ __forceinline__ float gelu_exact(float v) {
    return 0.5f * v * (1.0f + erff(v * 0.70710678118654752440f));
}

__device__ __forceinline__ float f2tf_f(float f) {
    unsigned u;
    asm("cvt.rna.tf32.f32 %0, %1;" : "=r"(u) : "f"(f));
    return __uint_as_float(u);
}

__device__ __forceinline__ void mma_tf32(float c[4], const float4& a, const float2& b) {
    const unsigned* A = reinterpret_cast<const unsigned*>(&a);
    const unsigned* Bv = reinterpret_cast<const unsigned*>(&b);
    asm volatile(
        "mma.sync.aligned.m16n8k8.row.col.f32.tf32.tf32.f32 "
        "{%0,%1,%2,%3},{%4,%5,%6,%7},{%8,%9},{%0,%1,%2,%3};\n"
        : "+f"(c[0]), "+f"(c[1]), "+f"(c[2]), "+f"(c[3])
        : "r"(A[0]), "r"(A[1]), "r"(A[2]), "r"(A[3]), "r"(Bv[0]), "r"(Bv[1]));
}
} // namespace

// device-global scratch (no runtime allocation)
// g_t1: stage-1 output in tiled A-frag layout:
//   float idx = ((rowtile*64 + kc*4 + ks)*32 + lane)*4 + rg
__device__ __align__(16) float g_t1[M_PIX * FF1];   // 128 MB
__device__ __align__(16) float g_weffB[H * WEFFB_F];
__device__ __align__(16) float g_hw1B[HW1B_F];
__device__ __align__(16) float g_fw1B[FW1B_F];
__device__ __align__(16) float g_fw2B[FW2B_F];
__device__ __align__(16) float g_fw3B[FW3B_F];

// =====================================================================
// prep: fold psi into disco_w per latitude (B-frag layout, rounded)
// =====================================================================
__global__ void prep_weffB(const float* __restrict__ dw,
                           const float* __restrict__ psi) {
    const int h = blockIdx.x;
    for (int e = threadIdx.x; e < WEFFB_F; e += blockDim.x) {
        int half = e & 1, t = e >> 1;
        int lane = t & 31; t >>= 5;
        int ks = t % 7, nt = t / 7;
        int g = lane >> 2, tg = lane & 3;
        int p = ks * 8 + tg + 4 * half;
        int s = nt * 8 + g;
        float acc = 0.f;
        if (p < PP) {
            #pragma unroll
            for (int k = 0; k < K; k++)
                acc += dw[s * K + k] * psi[(k * H + h) * PP + p];
        }
        g_weffB[h * WEFFB_F + e] = f2tf_f(acc);
    }
}

// =====================================================================
// prep: hw1 / fw1 / fw3 into B-frag layouts, rounded (merged kernel)
// =====================================================================
__global__ void prep_small(const float* __restrict__ hw1,
                           const float* __restrict__ fw1,
                           const float* __restrict__ fw3) {
    int e = blockIdx.x * blockDim.x + threadIdx.x;
    if (e < HW1B_F) {
        int half = e & 1, t = e >> 1;
        int lane = t & 31; t >>= 5;
        int ks = t & 7; t >>= 3;
        int nt = t & 3; int n = t >> 2;
        int g = lane >> 2, tg = lane & 3;
        int s = ks * 8 + tg + 4 * half;
        int o = nt * 8 + g;
        g_hw1B[e] = f2tf_f(hw1[(n * SH + s) * 32 + o]);
        return;
    }
    e -= HW1B_F;
    if (e < FW1B_F) {
        int half = e & 1, t = e >> 1;
        int lane = t & 31; t >>= 5;
        int ks = t % 5, nt = t / 5;
        int g = lane >> 2, tg = lane & 3;
        int k = ks * 8 + tg + 4 * half;
        int n = nt * 8 + g;
        g_fw1B[e] = (k < MD) ? f2tf_f(fw1[k * FF1 + n]) : 0.f;
        return;
    }
    e -= FW1B_F;
    if (e < FW3B_F) {
        int half = e & 1, t = e >> 1;
        int lane = t & 31; t >>= 5;
        int ks = t & 31, nt = t >> 5;
        int g = lane >> 2, tg = lane & 3;
        int k = ks * 8 + tg + 4 * half;
        int n = nt * 8 + g;
        g_fw3B[e] = f2tf_f(fw3[k * LD + n]);
    }
}

// =====================================================================
// prep: fw2 into per-chunk B-frag layout, rounded
// =====================================================================
__global__ void prep_fw2B(const float* __restrict__ fw2) {
    int e = blockIdx.x * blockDim.x + threadIdx.x;
    if (e >= FW2B_F) return;
    int kc = e >> 13, r = e & 8191;
    int half = r & 1; r >>= 1;
    int lane = r & 31; r >>= 5;
    int ks = r & 3; int nt = r >> 2;
    int g = lane >> 2, tg = lane & 3;
    int k = kc * 32 + ks * 8 + tg + 4 * half;
    int n = nt * 8 + g;
    g_fw2B[e] = f2tf_f(fw2[k * FF2 + n]);
}

// =====================================================================
// disco conv + head MLP + residual (tf32 mma) — R10 version (measured
// 252 us): 7-row stencil, predicated a-build, 39.4 KB smem.
// =====================================================================
__global__ __launch_bounds__(TAD, 2) void disco_head_mma(
    const float* __restrict__ x,   const float* __restrict__ db,
    const float* __restrict__ hb1, const float* __restrict__ hw2,
    const float* __restrict__ hb2, float* __restrict__ out)
{
    extern __shared__ float sm[];
    float* sx   = sm + OFF_SX;
    float* sxc  = sm + OFF_SXC;
    float* sdb  = sm + OFF_SDB;
    float* shb1 = sm + OFF_HB1;
    float* shw2 = sm + OFF_HW2;
    float* shb2 = sm + OFF_HB2;

    const int tid = threadIdx.x;
    const int lane = tid & 31, mt = tid >> 5;    // mt 0..7
    const int g  = lane >> 2, tg = lane & 3;
    const int w0 = blockIdx.x * TW;
    const int h  = blockIdx.y;
    const int b  = blockIdx.z;

    if (tid < SH) sdb[tid] = db[tid];
    if (tid < NH * 32) { shb1[tid] = hb1[tid]; shw2[tid] = hw2[tid]; }
    if (tid < NH) shb2[tid] = hb2[tid];

    // stencil tile: rounded into sx; exact center taps into sxc (residual)
    for (int i = tid; i < LD * P * XCOLS; i += TAD) {
        int ld = i & 31; int pos = i >> 5;
        int r = pos / XCOLS, c = pos % XCOLS;
        int lat = h + r - R; lat = lat < 0 ? 0 : (lat > H - 1 ? H - 1 : lat);
        int lon = (w0 + c - R + W) & (W - 1);
        float v = x[((b * H + lat) * W + lon) * MD + ld];
        sx[(ld * P + r) * XCOLS + c] = f2tf_f(v);
        if (r == R && c >= R && c < R + TW) sxc[ld * TW + (c - R)] = v;
    }
    for (int i = tid; i < TW * 2; i += TAD) {
        int px = i >> 1, j = i & 1;
        int gi = ((b * H + h) * W + (w0 + px)) * MD + LD + j;
        out[gi] = x[gi];
    }
    __syncthreads();

    // warp mt owns tiles t0=2mt, t1=2mt+1 -> same head nh = mt>>1,
    // rows = lds ldA..ldA+3 where ldA = nh*8 + 4*(mt&1)
    const int nh  = mt >> 1;
    const int ldA = nh * 8 + 4 * (mt & 1);
    const int px  = g;
    const int base0 = (ldA + 0) * P * XCOLS;
    const int base1 = (ldA + 1) * P * XCOLS;
    const int base2 = (ldA + 2) * P * XCOLS;
    const int base3 = (ldA + 3) * P * XCOLS;

    int roff0[7], roff1[7]; bool ok0[7], ok1[7];
    #pragma unroll
    for (int ks = 0; ks < 7; ks++) {
        int p0 = ks * 8 + tg, p1 = p0 + 4;
        ok0[ks] = p0 < PP; ok1[ks] = p1 < PP;
        roff0[ks] = ok0[ks] ? (p0 / 7) * XCOLS + (p0 % 7) : 0;
        roff1[ks] = ok1[ks] ? (p1 / 7) * XCOLS + (p1 % 7) : 0;
    }

    const float2* swB2  = reinterpret_cast<const float2*>(g_weffB) + (long)h * (WEFFB_F / 2);
    const float2* hw1b2 = reinterpret_cast<const float2*>(g_hw1B);

    // shuffle sources for C-frag -> A-frag relayout
    const int src0 = (lane & ~3) | (tg >> 1);
    const int src1 = src0 + 2;
    const bool odd = (tg & 1);

    for (int grp = 0; grp < NGRP; grp++) {
        const int cbase = grp * PIX + px;
        const int cb0 = base0 + cbase, cb1 = base1 + cbase;
        const int cb2 = base2 + cbase, cb3 = base3 + cbase;

        // phase 1: d = taps @ weff  (two m16 tiles, N=64, K=56)
        float c1[2][8][4] = {};
        #pragma unroll
        for (int ks = 0; ks < 7; ks++) {
            float4 a0, a1;
            a0.x = ok0[ks] ? sx[cb0 + roff0[ks]] : 0.f;
            a0.y = ok0[ks] ? sx[cb1 + roff0[ks]] : 0.f;
            a0.z = ok1[ks] ? sx[cb0 + roff1[ks]] : 0.f;
            a0.w = ok1[ks] ? sx[cb1 + roff1[ks]] : 0.f;
            a1.x = ok0[ks] ? sx[cb2 + roff0[ks]] : 0.f;
            a1.y = ok0[ks] ? sx[cb3 + roff0[ks]] : 0.f;
            a1.z = ok1[ks] ? sx[cb2 + roff1[ks]] : 0.f;
            a1.w = ok1[ks] ? sx[cb3 + roff1[ks]] : 0.f;
            #pragma unroll
            for (int nt = 0; nt < 8; nt++) {
                float2 bb = __ldg(&swB2[(nt * 7 + ks) * 32 + lane]);
                mma_tf32(c1[0][nt], a0, bb);
                mma_tf32(c1[1][nt], a1, bb);
            }
        }

        // phase 2 fused: per k8-block, bias+round, shuffle C->A frag (both
        // tiles), then each hw1 fragment load feeds 2 MMAs.
        float c2[2][4][4] = {};
        #pragma unroll
        for (int ks = 0; ks < 8; ks++) {
            const int scol = ks * 8 + 2 * tg;
            const float b0 = sdb[scol], b1 = sdb[scol + 1];
            float4 af[2];
            #pragma unroll
            for (int t = 0; t < 2; t++) {
                const float y0 = f2tf_f(c1[t][ks][0] + b0);
                const float y1 = f2tf_f(c1[t][ks][1] + b1);
                const float y2 = f2tf_f(c1[t][ks][2] + b0);
                const float y3 = f2tf_f(c1[t][ks][3] + b1);
                const float u0 = __shfl_sync(0xffffffffu, y0, src0);
                const float u1 = __shfl_sync(0xffffffffu, y1, src0);
                const float u2 = __shfl_sync(0xffffffffu, y2, src0);
                const float u3 = __shfl_sync(0xffffffffu, y3, src0);
                const float v0 = __shfl_sync(0xffffffffu, y0, src1);
                const float v1 = __shfl_sync(0xffffffffu, y1, src1);
                const float v2 = __shfl_sync(0xffffffffu, y2, src1);
                const float v3 = __shfl_sync(0xffffffffu, y3, src1);
                af[t].x = odd ? u1 : u0;
                af[t].y = odd ? u3 : u2;
                af[t].z = odd ? v1 : v0;
                af[t].w = odd ? v3 : v2;
            }
            #pragma unroll
            for (int nt2 = 0; nt2 < 4; nt2++) {
                float2 bb = __ldg(&hw1b2[((nh * 4 + nt2) * 8 + ks) * 32 + lane]);
                mma_tf32(c2[0][nt2], af[0], bb);
                mma_tf32(c2[1][nt2], af[1], bb);
            }
        }

        // epilogue 2: gelu + hw2 dot + lane reduce + residual (fp32 path)
        #pragma unroll
        for (int t = 0; t < 2; t++) {
            float part0 = 0.f, part1 = 0.f;
            #pragma unroll
            for (int nt2 = 0; nt2 < 4; nt2++) {
                const int o0 = nt2 * 8 + 2 * tg, o1 = o0 + 1;
                const float w0v = shw2[nh * 32 + o0], w1v = shw2[nh * 32 + o1];
                const float bb0 = shb1[nh * 32 + o0], bb1 = shb1[nh * 32 + o1];
                part0 += gelu_exact(c2[t][nt2][0] + bb0) * w0v
                       + gelu_exact(c2[t][nt2][1] + bb1) * w1v;
                part1 += gelu_exact(c2[t][nt2][2] + bb0) * w0v
                       + gelu_exact(c2[t][nt2][3] + bb1) * w1v;
            }
            part0 += __shfl_xor_sync(0xffffffffu, part0, 1);
            part0 += __shfl_xor_sync(0xffffffffu, part0, 2);
            part1 += __shfl_xor_sync(0xffffffffu, part1, 1);
            part1 += __shfl_xor_sync(0xffffffffu, part1, 2);
            if (tg == 0) {
                const int ld0 = ldA + 2 * t, ld1 = ld0 + 1;
                const int pxg = grp * PIX + px;
                const float v0 = part0 + shb2[nh] + sxc[ld0 * TW + pxg];
                const float v1 = part1 + shb2[nh] + sxc[ld1 * TW + pxg];
                const long o = ((long)(b * H + h) * W + w0 + pxg) * MD;
                out[o + ld0] = v0;
                out[o + ld1] = v1;
            }
        }
    }
}

// =====================================================================
// FFN stage 1: g_t1(frag) = gelu(out[:,:34] @ fw1 + fb1)
// =====================================================================
namespace {
constexpr int S1_AF = 4 * 5 * 32 * 4;   // 2560
constexpr int S1_BF = 32 * 5 * 32 * 2;  // 10240
}
__global__ __launch_bounds__(512) void ffn_s1(
    const float* __restrict__ xin, const float* __restrict__ fb1)
{
    extern __shared__ float sm[];
    float* sA = sm;
    float* sB = sm + S1_AF;
    const int tid = threadIdx.x, lane = tid & 31, w = tid >> 5;
    const int mw = w >> 2, nw = w & 3;
    const long r0 = (long)blockIdx.x * 64;
    const int  n0 = blockIdx.y * 256;

    {
        const int r = tid >> 3, rr7 = r & 7, rhi = (r >> 3) & 1, mt = r >> 4;
        const int kb = (tid & 7) * 5;
        #pragma unroll
        for (int j = 0; j < 5; j++) {
            const int k = kb + j;
            const float v = (k < MD) ? f2tf_f(xin[(r0 + r) * MD + k]) : 0.f;
            sA[((mt * 5 + (k >> 3)) * 32 + rr7 * 4 + (k & 3)) * 4
               + rhi + (((k >> 2) & 1) << 1)] = v;
        }
    }
    {
        const float4* src = reinterpret_cast<const float4*>(g_fw1B + blockIdx.y * S1_BF);
        float4* dst = reinterpret_cast<float4*>(sB);
        #pragma unroll
        for (int i = 0; i < 5; i++) dst[tid + i * 512] = src[tid + i * 512];
    }
    __syncthreads();

    float c[8][4] = {};
    #pragma unroll
    for (int ks = 0; ks < 5; ks++) {
        float4 a = reinterpret_cast<const float4*>(sA)[(mw * 5 + ks) * 32 + lane];
        #pragma unroll
        for (int ni = 0; ni < 8; ni++) {
            float2 bb = reinterpret_cast<const float2*>(sB)[((nw * 8 + ni) * 5 + ks) * 32 + lane];
            mma_tf32(c[ni], a, bb);
        }
    }

    const int g = lane >> 2, tg = lane & 3;
    const long rt = blockIdx.x * 4 + mw;
    float2* t1v2 = reinterpret_cast<float2*>(g_t1);
    #pragma unroll
    for (int ni = 0; ni < 8; ni++) {
        const int n = n0 + (nw * 8 + ni) * 8 + 2 * tg;
        const int kc = n >> 5, ks2 = (n >> 3) & 3;
        const int kk0 = n & 7, kk1 = kk0 + 1;
        const long base = (rt * 64 + kc * 4 + ks2) * 32;
        const int rgA = ((kk0 >> 2) & 1) << 1;
        const long i0 = (base + g * 4 + (kk0 & 3)) * 4 + rgA;
        const long i1 = (base + g * 4 + (kk1 & 3)) * 4 + rgA;
        const float b0 = fb1[n], b1 = fb1[n + 1];
        t1v2[i0 >> 1] = make_float2(f2tf_f(gelu_exact(c[ni][0] + b0)),
                                    f2tf_f(gelu_exact(c[ni][2] + b0)));
        t1v2[i1 >> 1] = make_float2(f2tf_f(gelu_exact(c[ni][1] + b1)),
                                    f2tf_f(gelu_exact(c[ni][3] + b1)));
    }
}

// =====================================================================
// FFN stages 2+3 fused. 96 KB smem -> 2 CTAs/SM (kept from R11):
// mainloop double-buffers in [0, 20480); afterwards sT2 overlays [0,16384)
// and fw3 frags are staged late into [16384, 24576).
// =====================================================================
namespace {
constexpr int S2_AF  = 4 * 4 * 32 * 4;     // 2048
constexpr int S2_BF  = 32 * 4 * 32 * 2;    // 8192
constexpr int S2_BUF = S2_AF + S2_BF;      // 10240
constexpr int ST2_F  = 4 * 32 * 32 * 4;    // 16384
constexpr int SF3_F  = 4 * 32 * 32 * 2;    // 8192
constexpr int S23_F  = ST2_F + SF3_F;      // 24576 floats = 96 KB
}
__global__ __launch_bounds__(512, 2) void ffn_s2s3(
    const float* __restrict__ fb2, const float* __restrict__ fb3,
    float* __restrict__ out)
{
    extern __shared__ float sm[];
    const int tid = threadIdx.x, lane = tid & 31, w = tid >> 5;
    const int mw = w >> 2, nw = w & 3;
    const long r0 = (long)blockIdx.x * 64;
    const long rt0 = (long)blockIdx.x * 4;

    float c[8][4] = {};
    const float4* t1v4 = reinterpret_cast<const float4*>(g_t1);
    const float4* fw2v4 = reinterpret_cast<const float4*>(g_fw2B);

    for (int kc = 0; kc < 16; kc++) {
        float* sA = sm + (kc & 1) * S2_BUF;
        float* sB = sA + S2_AF;
        reinterpret_cast<float4*>(sA)[tid] =
            t1v4[(rt0 + (tid >> 7)) * 2048 + kc * 128 + (tid & 127)];
        {
            float4* dst = reinterpret_cast<float4*>(sB);
            #pragma unroll
            for (int i = 0; i < 4; i++)
                dst[tid + i * 512] = fw2v4[kc * 2048 + tid + i * 512];
        }
        __syncthreads();
        #pragma unroll
        for (int ks = 0; ks < 4; ks++) {
            float4 a = reinterpret_cast<const float4*>(sA)[(mw * 4 + ks) * 32 + lane];
            #pragma unroll
            for (int ni = 0; ni < 8; ni++) {
                float2 bb = reinterpret_cast<const float2*>(sB)[((nw * 8 + ni) * 4 + ks) * 32 + lane];
                mma_tf32(c[ni], a, bb);
            }
        }
        __syncthreads();
    }

    // sT2 overlays the dead buffers; fw3 frags staged late behind it
    float* sT2 = sm;
    float* sf3 = sm + ST2_F;
    {
        const float4* src = reinterpret_cast<const float4*>(g_fw3B);
        float4* dst = reinterpret_cast<float4*>(sf3);
        #pragma unroll
        for (int i = 0; i < 4; i++) dst[tid + i * 512] = src[tid + i * 512];
    }
    float2* sT2v2 = reinterpret_cast<float2*>(sT2);
    const int g = lane >> 2, tg = lane & 3;
    #pragma unroll
    for (int ni = 0; ni < 8; ni++) {
        const int nt = nw * 8 + ni;
        const int n2 = nt * 8 + 2 * tg;
        const int kk0 = n2 & 7, kk1 = kk0 + 1;
        const int base = (mw * 32 + nt) * 32;
        const int rgA = ((kk0 >> 2) & 1) << 1;
        const int i0 = (base + g * 4 + (kk0 & 3)) * 4 + rgA;
        const int i1 = (base + g * 4 + (kk1 & 3)) * 4 + rgA;
        const float b0 = fb2[n2], b1 = fb2[n2 + 1];
        sT2v2[i0 >> 1] = make_float2(f2tf_f(gelu_exact(c[ni][0] + b0)),
                                     f2tf_f(gelu_exact(c[ni][2] + b0)));
        sT2v2[i1 >> 1] = make_float2(f2tf_f(gelu_exact(c[ni][1] + b1)),
                                     f2tf_f(gelu_exact(c[ni][3] + b1)));
    }
    __syncthreads();

    float c3[4] = {};
    #pragma unroll
    for (int ks = 0; ks < 32; ks++) {
        float4 a = reinterpret_cast<const float4*>(sT2)[(mw * 32 + ks) * 32 + lane];
        float2 bb = reinterpret_cast<const float2*>(sf3)[(nw * 32 + ks) * 32 + lane];
        mma_tf32(c3, a, bb);
    }

    const int col = nw * 8 + 2 * tg;
    const long rlo = r0 + mw * 16 + g, rhi = rlo + 8;
    const float b0 = fb3[col], b1 = fb3[col + 1];
    out[rlo * MD + col]     += c3[0] + b0;
    out[rlo * MD + col + 1] += c3[1] + b1;
    out[rhi * MD + col]     += c3[2] + b0;
    out[rhi * MD + col + 1] += c3[3] + b1;
}

extern "C" void kernel_launch(void* const* d_in, const int* in_sizes, int n_in,
                              void* d_out, int out_size) {
    const float* x   = (const float*)d_in[0];
    const float* psi = (const float*)d_in[1];
    const float* dw  = (const float*)d_in[2];
    const float* db  = (const float*)d_in[3];
    const float* hw1 = (const float*)d_in[4];
    const float* hb1 = (const float*)d_in[5];
    const float* hw2 = (const float*)d_in[6];
    const float* hb2 = (const float*)d_in[7];
    const float* fw1 = (const float*)d_in[8];
    const float* fb1 = (const float*)d_in[9];
    const float* fw2 = (const float*)d_in[10];
    const float* fb2 = (const float*)d_in[11];
    const float* fw3 = (const float*)d_in[12];
    const float* fb3 = (const float*)d_in[13];
    float* out = (float*)d_out;

    const size_t smD  = SMEM_D_F * sizeof(float);
    const size_t sm1  = (S1_AF + S1_BF) * sizeof(float);
    const size_t sm23 = S23_F * sizeof(float);
    cudaFuncSetAttribute(disco_head_mma, cudaFuncAttributeMaxDynamicSharedMemorySize, (int)smD);
    cudaFuncSetAttribute(ffn_s1, cudaFuncAttributeMaxDynamicSharedMemorySize, (int)sm1);
    cudaFuncSetAttribute(ffn_s2s3, cudaFuncAttributeMaxDynamicSharedMemorySize, (int)sm23);

    prep_weffB<<<H, 256>>>(dw, psi);
    prep_small<<<(HW1B_F + FW1B_F + FW3B_F + 255) / 256, 256>>>(hw1, fw1, fw3);
    prep_fw2B<<<FW2B_F / 256, 256>>>(fw2);
    disco_head_mma<<<dim3(W / TW, H, B), TAD, smD>>>(x, db, hb1, hw2, hb2, out);
    ffn_s1<<<dim3((unsigned)(M_PIX / 64), 2), 512, sm1>>>(out, fb1);
    ffn_s2s3<<<(unsigned)(M_PIX / 64), 512, sm23>>>(fb2, fb3, out);
}

// round 13
// speedup vs baseline: 1.2835x; 1.0430x over previous
#include <cuda_runtime.h>

namespace {
constexpr int B = 2, H = 128, W = 256, MD = 34, LD = 32;
constexpr int NH = 4, SH = 64, K = 25, P = 7, R = 3;
constexpr int FF1 = 512, FF2 = 256;
constexpr int PP = P * P; // 49
constexpr long M_PIX = (long)B * H * W; // 65536

// ---------------- disco mma kernel config (R10/R12, measured 251 us) --------
constexpr int TW   = 32;
constexpr int PIX  = 8;
constexpr int NGRP = TW / PIX;
constexpr int TAD  = 256;           // 8 warps, 2 m16-tiles per warp
constexpr int XCOLS = TW + 2 * R;   // 38

constexpr int WEFFB_F = 8 * 7 * 32 * 2;      // 3584
constexpr int HW1B_F  = 4 * 4 * 8 * 32 * 2;  // 8192
constexpr int FW1B_F  = 64 * 5 * 32 * 2;     // 20480 (k padded 34->40)
constexpr int FW2B_F  = 16 * 32 * 4 * 32 * 2;// 131072
constexpr int FW3B_F  = 4 * 32 * 32 * 2;     // 8192

constexpr int OFF_SX   = 0;                         // 8512
constexpr int OFF_SXC  = OFF_SX + LD * P * XCOLS;   // 1024
constexpr int OFF_SDB  = OFF_SXC + LD * TW;         // 64
constexpr int OFF_HB1  = OFF_SDB + SH;              // 128
constexpr int OFF_HW2  = OFF_HB1 + NH * 32;         // 128
constexpr int OFF_HB2  = OFF_HW2 + NH * 32;         // 4
constexpr int SMEM_D_F = OFF_HB2 + NH;              // 9860 fl = 39.4 KB

__device__ __forceinline__ float gelu_exact(float v) {
    return 0.5f * v * (1.0f + erff(v * 0.70710678118654752440f));
}

__device__ __forceinline__ float f2tf_f(float f) {
    unsigned u;
    asm("cvt.rna.tf32.f32 %0, %1;" : "=r"(u) : "f"(f));
    return __uint_as_float(u);
}

__device__ __forceinline__ void mma_tf32(float c[4], const float4& a, const float2& b) {
    const unsigned* A = reinterpret_cast<const unsigned*>(&a);
    const unsigned* Bv = reinterpret_cast<const unsigned*>(&b);
    asm volatile(
        "mma.sync.aligned.m16n8k8.row.col.f32.tf32.tf32.f32 "
        "{%0,%1,%2,%3},{%4,%5,%6,%7},{%8,%9},{%0,%1,%2,%3};\n"
        : "+f"(c[0]), "+f"(c[1]), "+f"(c[2]), "+f"(c[3])
        : "r"(A[0]), "r"(A[1]), "r"(A[2]), "r"(A[3]), "r"(Bv[0]), "r"(Bv[1]));
}
} // namespace

// device-global scratch (no runtime allocation) — g_t1 is GONE.
__device__ __align__(16) float g_weffB[H * WEFFB_F];
__device__ __align__(16) float g_hw1B[HW1B_F];
__device__ __align__(16) float g_fw1B[FW1B_F];
__device__ __align__(16) float g_fw2B[FW2B_F];
__device__ __align__(16) float g_fw3B[FW3B_F];

// =====================================================================
// prep: fold psi into disco_w per latitude (B-frag layout, rounded)
// =====================================================================
__global__ void prep_weffB(const float* __restrict__ dw,
                           const float* __restrict__ psi) {
    const int h = blockIdx.x;
    for (int e = threadIdx.x; e < WEFFB_F; e += blockDim.x) {
        int half = e & 1, t = e >> 1;
        int lane = t & 31; t >>= 5;
        int ks = t % 7, nt = t / 7;
        int g = lane >> 2, tg = lane & 3;
        int p = ks * 8 + tg + 4 * half;
        int s = nt * 8 + g;
        float acc = 0.f;
        if (p < PP) {
            #pragma unroll
            for (int k = 0; k < K; k++)
                acc += dw[s * K + k] * psi[(k * H + h) * PP + p];
        }
        g_weffB[h * WEFFB_F + e] = f2tf_f(acc);
    }
}

// =====================================================================
// prep: hw1 / fw1 / fw3 into B-frag layouts, rounded (merged kernel)
// =====================================================================
__global__ void prep_small(const float* __restrict__ hw1,
                           const float* __restrict__ fw1,
                           const float* __restrict__ fw3) {
    int e = blockIdx.x * blockDim.x + threadIdx.x;
    if (e < HW1B_F) {
        int half = e & 1, t = e >> 1;
        int lane = t & 31; t >>= 5;
        int ks = t & 7; t >>= 3;
        int nt = t & 3; int n = t >> 2;
        int g = lane >> 2, tg = lane & 3;
        int s = ks * 8 + tg + 4 * half;
        int o = nt * 8 + g;
        g_hw1B[e] = f2tf_f(hw1[(n * SH + s) * 32 + o]);
        return;
    }
    e -= HW1B_F;
    if (e < FW1B_F) {
        int half = e & 1, t = e >> 1;
        int lane = t & 31; t >>= 5;
        int ks = t % 5, nt = t / 5;
        int g = lane >> 2, tg = lane & 3;
        int k = ks * 8 + tg + 4 * half;
        int n = nt * 8 + g;
        g_fw1B[e] = (k < MD) ? f2tf_f(fw1[k * FF1 + n]) : 0.f;
        return;
    }
    e -= FW1B_F;
    if (e < FW3B_F) {
        int half = e & 1, t = e >> 1;
        int lane = t & 31; t >>= 5;
        int ks = t & 31, nt = t >> 5;
        int g = lane >> 2, tg = lane & 3;
        int k = ks * 8 + tg + 4 * half;
        int n = nt * 8 + g;
        g_fw3B[e] = f2tf_f(fw3[k * LD + n]);
    }
}

// =====================================================================
// prep: fw2 into per-chunk B-frag layout, rounded
// =====================================================================
__global__ void prep_fw2B(const float* __restrict__ fw2) {
    int e = blockIdx.x * blockDim.x + threadIdx.x;
    if (e >= FW2B_F) return;
    int kc = e >> 13, r = e & 8191;
    int half = r & 1; r >>= 1;
    int lane = r & 31; r >>= 5;
    int ks = r & 3; int nt = r >> 2;
    int g = lane >> 2, tg = lane & 3;
    int k = kc * 32 + ks * 8 + tg + 4 * half;
    int n = nt * 8 + g;
    g_fw2B[e] = f2tf_f(fw2[k * FF2 + n]);
}

// =====================================================================
// disco conv + head MLP + residual (tf32 mma) — R12 version, unchanged.
// =====================================================================
__global__ __launch_bounds__(TAD, 2) void disco_head_mma(
    const float* __restrict__ x,   const float* __restrict__ db,
    const float* __restrict__ hb1, const float* __restrict__ hw2,
    const float* __restrict__ hb2, float* __restrict__ out)
{
    extern __shared__ float sm[];
    float* sx   = sm + OFF_SX;
    float* sxc  = sm + OFF_SXC;
    float* sdb  = sm + OFF_SDB;
    float* shb1 = sm + OFF_HB1;
    float* shw2 = sm + OFF_HW2;
    float* shb2 = sm + OFF_HB2;

    const int tid = threadIdx.x;
    const int lane = tid & 31, mt = tid >> 5;
    const int g  = lane >> 2, tg = lane & 3;
    const int w0 = blockIdx.x * TW;
    const int h  = blockIdx.y;
    const int b  = blockIdx.z;

    if (tid < SH) sdb[tid] = db[tid];
    if (tid < NH * 32) { shb1[tid] = hb1[tid]; shw2[tid] = hw2[tid]; }
    if (tid < NH) shb2[tid] = hb2[tid];

    for (int i = tid; i < LD * P * XCOLS; i += TAD) {
        int ld = i & 31; int pos = i >> 5;
        int r = pos / XCOLS, c = pos % XCOLS;
        int lat = h + r - R; lat = lat < 0 ? 0 : (lat > H - 1 ? H - 1 : lat);
        int lon = (w0 + c - R + W) & (W - 1);
        float v = x[((b * H + lat) * W + lon) * MD + ld];
        sx[(ld * P + r) * XCOLS + c] = f2tf_f(v);
        if (r == R && c >= R && c < R + TW) sxc[ld * TW + (c - R)] = v;
    }
    for (int i = tid; i < TW * 2; i += TAD) {
        int px = i >> 1, j = i & 1;
        int gi = ((b * H + h) * W + (w0 + px)) * MD + LD + j;
        out[gi] = x[gi];
    }
    __syncthreads();

    const int nh  = mt >> 1;
    const int ldA = nh * 8 + 4 * (mt & 1);
    const int px  = g;
    const int base0 = (ldA + 0) * P * XCOLS;
    const int base1 = (ldA + 1) * P * XCOLS;
    const int base2 = (ldA + 2) * P * XCOLS;
    const int base3 = (ldA + 3) * P * XCOLS;

    int roff0[7], roff1[7]; bool ok0[7], ok1[7];
    #pragma unroll
    for (int ks = 0; ks < 7; ks++) {
        int p0 = ks * 8 + tg, p1 = p0 + 4;
        ok0[ks] = p0 < PP; ok1[ks] = p1 < PP;
        roff0[ks] = ok0[ks] ? (p0 / 7) * XCOLS + (p0 % 7) : 0;
        roff1[ks] = ok1[ks] ? (p1 / 7) * XCOLS + (p1 % 7) : 0;
    }

    const float2* swB2  = reinterpret_cast<const float2*>(g_weffB) + (long)h * (WEFFB_F / 2);
    const float2* hw1b2 = reinterpret_cast<const float2*>(g_hw1B);

    const int src0 = (lane & ~3) | (tg >> 1);
    const int src1 = src0 + 2;
    const bool odd = (tg & 1);

    for (int grp = 0; grp < NGRP; grp++) {
        const int cbase = grp * PIX + px;
        const int cb0 = base0 + cbase, cb1 = base1 + cbase;
        const int cb2 = base2 + cbase, cb3 = base3 + cbase;

        float c1[2][8][4] = {};
        #pragma unroll
        for (int ks = 0; ks < 7; ks++) {
            float4 a0, a1;
            a0.x = ok0[ks] ? sx[cb0 + roff0[ks]] : 0.f;
            a0.y = ok0[ks] ? sx[cb1 + roff0[ks]] : 0.f;
            a0.z = ok1[ks] ? sx[cb0 + roff1[ks]] : 0.f;
            a0.w = ok1[ks] ? sx[cb1 + roff1[ks]] : 0.f;
            a1.x = ok0[ks] ? sx[cb2 + roff0[ks]] : 0.f;
            a1.y = ok0[ks] ? sx[cb3 + roff0[ks]] : 0.f;
            a1.z = ok1[ks] ? sx[cb2 + roff1[ks]] : 0.f;
            a1.w = ok1[ks] ? sx[cb3 + roff1[ks]] : 0.f;
            #pragma unroll
            for (int nt = 0; nt < 8; nt++) {
                float2 bb = __ldg(&swB2[(nt * 7 + ks) * 32 + lane]);
                mma_tf32(c1[0][nt], a0, bb);
                mma_tf32(c1[1][nt], a1, bb);
            }
        }

        float c2[2][4][4] = {};
        #pragma unroll
        for (int ks = 0; ks < 8; ks++) {
            const int scol = ks * 8 + 2 * tg;
            const float b0 = sdb[scol], b1 = sdb[scol + 1];
            float4 af[2];
            #pragma unroll
            for (int t = 0; t < 2; t++) {
                const float y0 = f2tf_f(c1[t][ks][0] + b0);
                const float y1 = f2tf_f(c1[t][ks][1] + b1);
                const float y2 = f2tf_f(c1[t][ks][2] + b0);
                const float y3 = f2tf_f(c1[t][ks][3] + b1);
                const float u0 = __shfl_sync(0xffffffffu, y0, src0);
                const float u1 = __shfl_sync(0xffffffffu, y1, src0);
                const float u2 = __shfl_sync(0xffffffffu, y2, src0);
                const float u3 = __shfl_sync(0xffffffffu, y3, src0);
                const float v0 = __shfl_sync(0xffffffffu, y0, src1);
                const float v1 = __shfl_sync(0xffffffffu, y1, src1);
                const float v2 = __shfl_sync(0xffffffffu, y2, src1);
                const float v3 = __shfl_sync(0xffffffffu, y3, src1);
                af[t].x = odd ? u1 : u0;
                af[t].y = odd ? u3 : u2;
                af[t].z = odd ? v1 : v0;
                af[t].w = odd ? v3 : v2;
            }
            #pragma unroll
            for (int nt2 = 0; nt2 < 4; nt2++) {
                float2 bb = __ldg(&hw1b2[((nh * 4 + nt2) * 8 + ks) * 32 + lane]);
                mma_tf32(c2[0][nt2], af[0], bb);
                mma_tf32(c2[1][nt2], af[1], bb);
            }
        }

        #pragma unroll
        for (int t = 0; t < 2; t++) {
            float part0 = 0.f, part1 = 0.f;
            #pragma unroll
            for (int nt2 = 0; nt2 < 4; nt2++) {
                const int o0 = nt2 * 8 + 2 * tg, o1 = o0 + 1;
                const float w0v = shw2[nh * 32 + o0], w1v = shw2[nh * 32 + o1];
                const float bb0 = shb1[nh * 32 + o0], bb1 = shb1[nh * 32 + o1];
                part0 += gelu_exact(c2[t][nt2][0] + bb0) * w0v
                       + gelu_exact(c2[t][nt2][1] + bb1) * w1v;
                part1 += gelu_exact(c2[t][nt2][2] + bb0) * w0v
                       + gelu_exact(c2[t][nt2][3] + bb1) * w1v;
            }
            part0 += __shfl_xor_sync(0xffffffffu, part0, 1);
            part0 += __shfl_xor_sync(0xffffffffu, part0, 2);
            part1 += __shfl_xor_sync(0xffffffffu, part1, 1);
            part1 += __shfl_xor_sync(0xffffffffu, part1, 2);
            if (tg == 0) {
                const int ld0 = ldA + 2 * t, ld1 = ld0 + 1;
                const int pxg = grp * PIX + px;
                const float v0 = part0 + shb2[nh] + sxc[ld0 * TW + pxg];
                const float v1 = part1 + shb2[nh] + sxc[ld1 * TW + pxg];
                const long o = ((long)(b * H + h) * W + w0 + pxg) * MD;
                out[o + ld0] = v0;
                out[o + ld1] = v1;
            }
        }
    }
}

// =====================================================================
// FFN fully fused: per 64-row tile, t1 chunks are computed on the fly
// (5 MMAs/warp/chunk from register-resident x frags), exchanged through
// a 2048-float smem buffer into stage-2 A-frags, accumulated against
// fw2 chunks; then t2 -> smem frags, fw3 applied, residual added.
// No g_t1, no separate s1 kernel.
//
// smem (floats):
//   mainloop: buf[b] at b*10240: t1c frags [0,2048) + fw2 chunk [2048,10240)
//   post:     sT2 [0,16384) + sf3 [16384,24576)   (overlays the buffers)
//   always:   sfb1 [24576, 25088)
// =====================================================================
namespace {
constexpr int FB_BUF  = 10240;                 // 2048 t1c + 8192 fw2
constexpr int FST2_F  = 4 * 32 * 32 * 4;       // 16384
constexpr int FSF3    = FST2_F;                // sf3 offset
constexpr int FFB1    = 24576;                 // fb1 offset
constexpr int SFN_F   = FFB1 + FF1;            // 25088 floats = 100.4 KB
}
__global__ __launch_bounds__(512) void ffn_fused(
    const float* __restrict__ xin, const float* __restrict__ fb1,
    const float* __restrict__ fb2, const float* __restrict__ fb3,
    float* __restrict__ out)
{
    extern __shared__ float sm[];
    float* sfb1 = sm + FFB1;
    const int tid = threadIdx.x, lane = tid & 31, w = tid >> 5;
    const int mw = w >> 2, nw = w & 3;
    const int g = lane >> 2, tg = lane & 3;
    const long r0 = (long)blockIdx.x * 64;

    sfb1[tid] = fb1[tid];   // 512 threads, 512 entries

    // stage x A-frags (64 rows x 40 k, rounded) into sm[0,2560), then
    // each warp pulls its 5 float4 fragments into registers.
    {
        const int r = tid >> 3, rr7 = r & 7, rhi = (r >> 3) & 1, mt = r >> 4;
        const int kb = (tid & 7) * 5;
        #pragma unroll
        for (int j = 0; j < 5; j++) {
            const int k = kb + j;
            const float v = (k < MD) ? f2tf_f(xin[(r0 + r) * MD + k]) : 0.f;
            sm[((mt * 5 + (k >> 3)) * 32 + rr7 * 4 + (k & 3)) * 4
               + rhi + (((k >> 2) & 1) << 1)] = v;
        }
    }
    __syncthreads();
    float4 xfrag[5];
    #pragma unroll
    for (int ks = 0; ks < 5; ks++)
        xfrag[ks] = reinterpret_cast<const float4*>(sm)[(mw * 5 + ks) * 32 + lane];
    __syncthreads();

    float c2[8][4] = {};
    const float2* fw1b2 = reinterpret_cast<const float2*>(g_fw1B);
    const float4* fw2v4 = reinterpret_cast<const float4*>(g_fw2B);

    for (int kc = 0; kc < 16; kc++) {
        float* buf  = sm + (kc & 1) * FB_BUF;
        float* st1c = buf;
        float* sB   = buf + 2048;

        // fw2 chunk staging (issued early so LDG overlaps the t1c compute)
        {
            float4* dst = reinterpret_cast<float4*>(sB);
            #pragma unroll
            for (int i = 0; i < 4; i++)
                dst[tid + i * 512] = fw2v4[kc * 2048 + tid + i * 512];
        }

        // t1 chunk: warp (mw,nw) computes its m16 x n8 tile (cols kc*32+nw*8..)
        float c1[4] = {};
        #pragma unroll
        for (int ks = 0; ks < 5; ks++) {
            float2 bb = __ldg(&fw1b2[(((kc * 4 + nw) * 5) + ks) * 32 + lane]);
            mma_tf32(c1, xfrag[ks], bb);
        }
        // bias + gelu + round, scatter into A-frag slice nw of row tile mw
        {
            const int n = kc * 32 + nw * 8 + 2 * tg;
            const float b0 = sfb1[n], b1 = sfb1[n + 1];
            const int kk0 = 2 * tg, kk1 = kk0 + 1;
            const int i0 = mw * 512 + (nw * 32 + g * 4 + (kk0 & 3)) * 4 + ((kk0 >> 2) << 1);
            const int i1 = mw * 512 + (nw * 32 + g * 4 + (kk1 & 3)) * 4 + ((kk1 >> 2) << 1);
            *reinterpret_cast<float2*>(st1c + i0) =
                make_float2(f2tf_f(gelu_exact(c1[0] + b0)),
                            f2tf_f(gelu_exact(c1[2] + b0)));
            *reinterpret_cast<float2*>(st1c + i1) =
                make_float2(f2tf_f(gelu_exact(c1[1] + b1)),
                            f2tf_f(gelu_exact(c1[3] + b1)));
        }
        __syncthreads();

        // stage-2 MMAs: 4 k-slices x 8 n8 tiles
        #pragma unroll
        for (int ks = 0; ks < 4; ks++) {
            float4 a = reinterpret_cast<const float4*>(st1c)[(mw * 4 + ks) * 32 + lane];
            #pragma unroll
            for (int ni = 0; ni < 8; ni++) {
                float2 bb = reinterpret_cast<const float2*>(sB)[((nw * 8 + ni) * 4 + ks) * 32 + lane];
                mma_tf32(c2[ni], a, bb);
            }
        }
    }
    __syncthreads();

    // t2 -> smem A-frags (rounded); fw3 frags staged late behind it
    float* sT2 = sm;
    float* sf3 = sm + FSF3;
    {
        const float4* src = reinterpret_cast<const float4*>(g_fw3B);
        float4* dst = reinterpret_cast<float4*>(sf3);
        #pragma unroll
        for (int i = 0; i < 4; i++) dst[tid + i * 512] = src[tid + i * 512];
    }
    float2* sT2v2 = reinterpret_cast<float2*>(sT2);
    #pragma unroll
    for (int ni = 0; ni < 8; ni++) {
        const int nt = nw * 8 + ni;
        const int n2 = nt * 8 + 2 * tg;
        const int kk0 = n2 & 7, kk1 = kk0 + 1;
        const int base = (mw * 32 + nt) * 32;
        const int rgA = ((kk0 >> 2) & 1) << 1;
        const int i0 = (base + g * 4 + (kk0 & 3)) * 4 + rgA;
        const int i1 = (base + g * 4 + (kk1 & 3)) * 4 + rgA;
        const float b0 = fb2[n2], b1 = fb2[n2 + 1];
        sT2v2[i0 >> 1] = make_float2(f2tf_f(gelu_exact(c2[ni][0] + b0)),
                                     f2tf_f(gelu_exact(c2[ni][2] + b0)));
        sT2v2[i1 >> 1] = make_float2(f2tf_f(gelu_exact(c2[ni][1] + b1)),
                                     f2tf_f(gelu_exact(c2[ni][3] + b1)));
    }
    __syncthreads();

    // stage 3: [64,256] x [256,32] + bias + residual
    float c3[4] = {};
    #pragma unroll
    for (int ks = 0; ks < 32; ks++) {
        float4 a = reinterpret_cast<const float4*>(sT2)[(mw * 32 + ks) * 32 + lane];
        float2 bb = reinterpret_cast<const float2*>(sf3)[(nw * 32 + ks) * 32 + lane];
        mma_tf32(c3, a, bb);
    }

    const int col = nw * 8 + 2 * tg;
    const long rlo = r0 + mw * 16 + g, rhi = rlo + 8;
    const float b0 = fb3[col], b1 = fb3[col + 1];
    out[rlo * MD + col]     += c3[0] + b0;
    out[rlo * MD + col + 1] += c3[1] + b1;
    out[rhi * MD + col]     += c3[2] + b0;
    out[rhi * MD + col + 1] += c3[3] + b1;
}

extern "C" void kernel_launch(void* const* d_in, const int* in_sizes, int n_in,
                              void* d_out, int out_size) {
    const float* x   = (const float*)d_in[0];
    const float* psi = (const float*)d_in[1];
    const float* dw  = (const float*)d_in[2];
    const float* db  = (const float*)d_in[3];
    const float* hw1 = (const float*)d_in[4];
    const float* hb1 = (const float*)d_in[5];
    const float* hw2 = (const float*)d_in[6];
    const float* hb2 = (const float*)d_in[7];
    const float* fw1 = (const float*)d_in[8];
    const float* fb1 = (const float*)d_in[9];
    const float* fw2 = (const float*)d_in[10];
    const float* fb2 = (const float*)d_in[11];
    const float* fw3 = (const float*)d_in[12];
    const float* fb3 = (const float*)d_in[13];
    float* out = (float*)d_out;

    const size_t smD  = SMEM_D_F * sizeof(float);
    const size_t smF  = SFN_F * sizeof(float);
    cudaFuncSetAttribute(disco_head_mma, cudaFuncAttributeMaxDynamicSharedMemorySize, (int)smD);
    cudaFuncSetAttribute(ffn_fused, cudaFuncAttributeMaxDynamicSharedMemorySize, (int)smF);

    prep_weffB<<<H, 256>>>(dw, psi);
    prep_small<<<(HW1B_F + FW1B_F + FW3B_F + 255) / 256, 256>>>(hw1, fw1, fw3);
    prep_fw2B<<<FW2B_F / 256, 256>>>(fw2);
    disco_head_mma<<<dim3(W / TW, H, B), TAD, smD>>>(x, db, hb1, hw2, hb2, out);
    ffn_fused<<<(unsigned)(M_PIX / 64), 512, smF>>>(out, fb1, fb2, fb3, out);
}